// round 8
// baseline (speedup 1.0000x reference)
#include <cuda_runtime.h>
#include <cuda_fp16.h>
#include <math.h>
#include <stdint.h>

// Problem constants
#define BATCH 4
#define NTOK 4096
#define DIM 1024
#define NHEAD 16
#define HD 64
#define MROWS (BATCH * NTOK)          // 16384
#define SCALE 0.125f                  // HD^-0.5
#define NCHUNK 4                      // attn_pass1 token-range split

// ---------------------------------------------------------------------------
// Scratch buffers
// ---------------------------------------------------------------------------
__device__ __half g_x_h [MROWS * DIM];
__device__ __half g_hq_h[MROWS * DIM];
__device__ __half g_hk_h[MROWS * DIM];
__device__ __half g_y_h [MROWS * DIM];
__device__ float g_q [MROWS * DIM];
__device__ float g_k [MROWS * DIM];
__device__ float g_v [MROWS * DIM];
__device__ float g_g [MROWS * DIM];
__device__ float g_A [BATCH * NHEAD * HD * HD];
__device__ float g_z [BATCH * NHEAD * HD];
__device__ float g_Ap[NCHUNK * BATCH * NHEAD * HD * HD];
__device__ float g_zp[NCHUNK * BATCH * NHEAD * HD];
__device__ __half g_w_h [7 * DIM * DIM];   // fp16 weights

// ---------------------------------------------------------------------------
// PTX helpers (sm_80+ portable)
// ---------------------------------------------------------------------------
__device__ __forceinline__ uint32_t smem_u32(const void* p) {
    uint32_t a;
    asm("{ .reg .u64 t; cvta.to.shared.u64 t, %1; cvt.u32.u64 %0, t; }" : "=r"(a) : "l"(p));
    return a;
}
#define SWZ(o) ((o) ^ (((o) >> 3) & 0x70))

__device__ __forceinline__ void cp16(uint32_t saddr, const void* g) {
    asm volatile("cp.async.cg.shared.global [%0], [%1], 16;" :: "r"(saddr), "l"(g));
}
#define CP_COMMIT() asm volatile("cp.async.commit_group;" ::: "memory")
#define CP_WAIT(N)  asm volatile("cp.async.wait_group %0;" :: "n"(N) : "memory")

#define LDSM4(r, a) \
    asm volatile("ldmatrix.sync.aligned.m8n8.x4.shared.b16 {%0,%1,%2,%3}, [%4];" \
        : "=r"((r)[0]), "=r"((r)[1]), "=r"((r)[2]), "=r"((r)[3]) : "r"(a))

#define MMA16816F(c, a, b) \
    asm volatile("mma.sync.aligned.m16n8k16.row.col.f32.f16.f16.f32 " \
        "{%0,%1,%2,%3}, {%4,%5,%6,%7}, {%8,%9}, {%0,%1,%2,%3};" \
        : "+f"((c)[0]), "+f"((c)[1]), "+f"((c)[2]), "+f"((c)[3]) \
        : "r"((a)[0]), "r"((a)[1]), "r"((a)[2]), "r"((a)[3]), \
          "r"((b)[0]), "r"((b)[1]))

// ---------------------------------------------------------------------------
// Activations
// ---------------------------------------------------------------------------
__device__ __forceinline__ float gelu_f(float x) {
    return 0.5f * x * (1.0f + erff(x * 0.70710678118654752440f));
}
__device__ __forceinline__ float softplus_f(float x) {
    return fmaxf(x, 0.0f) + log1pf(__expf(-fabsf(x)));
}
__device__ __forceinline__ uint32_t pack2h(float a, float b) {
    __half2 h = __halves2half2(__float2half_rn(a), __float2half_rn(b));
    return *(uint32_t*)&h;
}

// ---------------------------------------------------------------------------
// fp32 -> fp16 convert (x and weights)
// ---------------------------------------------------------------------------
__global__ __launch_bounds__(256)
void conv_f2h(const float* __restrict__ src, __half* __restrict__ dst, int n4)
{
    const int stride = gridDim.x * blockDim.x;
    for (int i = blockIdx.x * blockDim.x + threadIdx.x; i < n4; i += stride) {
        float4 v = ((const float4*)src)[i];
        uint2 d;
        d.x = pack2h(v.x, v.y);
        d.y = pack2h(v.z, v.w);
        ((uint2*)dst)[i] = d;
    }
}

// ---------------------------------------------------------------------------
// HMMA fp16 single-term GEMM: C[M,1024] = act(A @ W^T + bias)
// CTA tile 128x128, BK=64, 3-stage cp.async pipeline, 8 warps (4m x 2n),
// warp tile 32x64, 2 CTAs/SM (96KB smem each).
// ---------------------------------------------------------------------------
#define TILE_B 16384
#define STAGE_B (2 * TILE_B)            // A, W
#define NSTAGE 3
#define GSMEM_TOTAL (NSTAGE * STAGE_B)  // 98304

__global__ __launch_bounds__(256, 2)
void gemm_mma(const __half* __restrict__ A, const __half* __restrict__ Wh,
              const float* __restrict__ bias, int act, int outmode,
              float* __restrict__ Cf, __half* __restrict__ Ch)
{
    extern __shared__ char smem[];
    const uint32_t sb = smem_u32(smem);
    const int t    = threadIdx.x;
    const int lane = t & 31;
    const int w    = t >> 5;
    const int wm   = w & 3;        // 4 m-warps
    const int wn   = w >> 2;       // 2 n-warps
    const int m0   = blockIdx.y * 128;
    const int n0   = blockIdx.x * 128;

    const int lrow = t >> 3;       // 0..31
    const int lu   = t & 7;

    auto issue = [&](int stage, int kc) {
        const uint32_t sbase = sb + stage * STAGE_B;
        const int kbase = kc * 64 + lu * 8;
#pragma unroll
        for (int i = 0; i < 4; i++) {
            const int row = lrow + i * 32;
            const uint32_t soff = SWZ((uint32_t)(row * 128 + lu * 16));
            cp16(sbase + soff,          A  + (size_t)(m0 + row) * DIM + kbase);
            cp16(sbase + TILE_B + soff, Wh + (size_t)(n0 + row) * DIM + kbase);
        }
        CP_COMMIT();
    };

    issue(0, 0);
    issue(1, 1);

    float acc[2][8][4];
#pragma unroll
    for (int im = 0; im < 2; im++)
#pragma unroll
        for (int in = 0; in < 8; in++)
#pragma unroll
            for (int j = 0; j < 4; j++) acc[im][in][j] = 0.0f;

    const int g  = lane >> 3;
    const int rr = lane & 7;

    for (int kc = 0; kc < 16; kc++) {
        if (kc == 15) { CP_WAIT(0); } else { CP_WAIT(1); }
        __syncthreads();
        if (kc + 2 < 16) issue((kc + 2) % NSTAGE, kc + 2);

        const uint32_t st = sb + (kc % NSTAGE) * STAGE_B;
#pragma unroll
        for (int kk = 0; kk < 4; kk++) {
            const int ku = kk * 2 + (g >> 1);
            uint32_t ah[2][4];
#pragma unroll
            for (int im = 0; im < 2; im++) {
                const int row = wm * 32 + im * 16 + (g & 1) * 8 + rr;
                const uint32_t off = SWZ((uint32_t)(row * 128 + ku * 16));
                LDSM4(ah[im], st + off);
            }
            uint32_t bh[8][2];
#pragma unroll
            for (int in2 = 0; in2 < 4; in2++) {
                const int row = wn * 64 + in2 * 16 + (g & 1) * 8 + rr;
                const uint32_t off = SWZ((uint32_t)(row * 128 + ku * 16));
                uint32_t qh[4];
                LDSM4(qh, st + TILE_B + off);
                bh[2 * in2][0] = qh[0]; bh[2 * in2][1] = qh[2];
                bh[2 * in2 + 1][0] = qh[1]; bh[2 * in2 + 1][1] = qh[3];
            }
#pragma unroll
            for (int im = 0; im < 2; im++)
#pragma unroll
                for (int in = 0; in < 8; in++)
                    MMA16816F(acc[im][in], ah[im], bh[in]);
        }
    }

    // ------ epilogue ------
    const int r0 = lane >> 2;
    const int c0 = (lane & 3) * 2;
#pragma unroll
    for (int im = 0; im < 2; im++) {
#pragma unroll
        for (int in = 0; in < 8; in++) {
            const int ncol = n0 + wn * 64 + in * 8 + c0;
            const float b0 = __ldg(&bias[ncol]);
            const float b1 = __ldg(&bias[ncol + 1]);
#pragma unroll
            for (int half = 0; half < 2; half++) {
                const int mrow = m0 + wm * 32 + im * 16 + r0 + half * 8;
                float v0 = acc[im][in][half * 2]     + b0;
                float v1 = acc[im][in][half * 2 + 1] + b1;
                if (act == 1)      { v0 = gelu_f(v0);     v1 = gelu_f(v1); }
                else if (act == 2) { v0 = softplus_f(v0); v1 = softplus_f(v1); }
                if (outmode == 0) {
                    *(float2*)(Cf + (size_t)mrow * DIM + ncol) = make_float2(v0, v1);
                } else {
                    *(__half2*)(Ch + (size_t)mrow * DIM + ncol) =
                        __halves2half2(__float2half_rn(v0), __float2half_rn(v1));
                }
            }
        }
    }
}

// ---------------------------------------------------------------------------
// Attention pass 1 (partial): grid (64 bh, NCHUNK)
// ---------------------------------------------------------------------------
__global__ __launch_bounds__(512)
void attn_pass1p(const float* __restrict__ q, const float* __restrict__ k,
                 float* __restrict__ Ap, float* __restrict__ Zp)
{
    const int bh = blockIdx.x;
    const int ch = blockIdx.y;
    const int b  = bh >> 4;
    const int h  = bh & 15;
    const float* qb = q + (size_t)b * NTOK * DIM + h * HD;
    const float* kb = k + (size_t)b * NTOK * DIM + h * HD;

    __shared__ float qs[64][64];
    __shared__ float ks[64][64];
    __shared__ float ksum[64];

    const int t  = threadIdx.x;
    const int n  = t >> 3;
    const int m0 = (t & 7) << 3;
    const int lr = t >> 3;
    const int lc = (t & 7) << 3;

    float acc[8] = {0, 0, 0, 0, 0, 0, 0, 0};
    float zacc = 0.0f;
    const bool zowner = ((t & 7) == 0);

    const int cbeg = ch * (NTOK / NCHUNK);
    const int cend = cbeg + (NTOK / NCHUNK);
    for (int c0 = cbeg; c0 < cend; c0 += 64) {
        const float* qrow = qb + (size_t)(c0 + lr) * DIM + lc;
        const float* krow = kb + (size_t)(c0 + lr) * DIM + lc;
        float4 qa = *(const float4*)(qrow);
        float4 qc = *(const float4*)(qrow + 4);
        float4 ka = *(const float4*)(krow);
        float4 kc = *(const float4*)(krow + 4);
        __syncthreads();
        *(float4*)&qs[lr][lc]     = qa;
        *(float4*)&qs[lr][lc + 4] = qc;
        *(float4*)&ks[lr][lc]     = ka;
        *(float4*)&ks[lr][lc + 4] = kc;
        __syncthreads();
        if (t < 64) {
            float s = 0.0f;
#pragma unroll
            for (int m = 0; m < 64; m++) s += ks[t][(m + t) & 63];
            ksum[t] = s;
        }
        __syncthreads();

#pragma unroll 4
        for (int c = 0; c < 64; c++) {
            float qv = qs[c][n];
            float4 k4a = *(const float4*)&ks[c][m0];
            float4 k4b = *(const float4*)&ks[c][m0 + 4];
            acc[0] += qv * k4a.x; acc[1] += qv * k4a.y;
            acc[2] += qv * k4a.z; acc[3] += qv * k4a.w;
            acc[4] += qv * k4b.x; acc[5] += qv * k4b.y;
            acc[6] += qv * k4b.z; acc[7] += qv * k4b.w;
            if (zowner) zacc += qv * ksum[c];
        }
    }

    float* Abh = Ap + ((size_t)ch * 64 + bh) * HD * HD;
#pragma unroll
    for (int j = 0; j < 8; j++)
        Abh[(m0 + j) * HD + n] = acc[j];
    if (zowner)
        Zp[((size_t)ch * 64 + bh) * HD + n] = zacc;
}

__global__ __launch_bounds__(256)
void attn_reduce(const float* __restrict__ Ap, const float* __restrict__ Zp,
                 float* __restrict__ gA, float* __restrict__ gZ)
{
    const int bh = blockIdx.x;
    const int t  = threadIdx.x;
    for (int i = t; i < HD * HD; i += 256) {
        float s = 0.0f;
#pragma unroll
        for (int c = 0; c < NCHUNK; c++)
            s += Ap[((size_t)c * 64 + bh) * HD * HD + i];
        gA[(size_t)bh * HD * HD + i] = s;
    }
    if (t < HD) {
        float s = 0.0f;
#pragma unroll
        for (int c = 0; c < NCHUNK; c++)
            s += Zp[((size_t)c * 64 + bh) * HD + t];
        gZ[bh * HD + t] = 1.0f / (SCALE * s + (float)DIM);
    }
}

// ---------------------------------------------------------------------------
// Attention pass 2 — writes scrambled gated output as fp16
// ---------------------------------------------------------------------------
__global__ __launch_bounds__(256)
void attn_pass2(const float* __restrict__ v, const float* __restrict__ gg,
                const float* __restrict__ gA, const float* __restrict__ gZ,
                __half* __restrict__ Yh)
{
    const int bh = blockIdx.x;
    const int b  = bh >> 4;
    const int h  = bh & 15;
    const int c0 = blockIdx.y * 64;

    __shared__ float As[HD * HD];
    __shared__ float vs[64][64];
    __shared__ float zs[64];

    const int t = threadIdx.x;

    const float4* Asrc = (const float4*)(gA + (size_t)bh * HD * HD);
#pragma unroll
    for (int i = t; i < HD * HD / 4; i += 256)
        ((float4*)As)[i] = Asrc[i];
    if (t < 64) zs[t] = gZ[bh * HD + t];

    {
        const int lr = t >> 2;
        const int lc = (t & 3) << 4;
        const float* vrow = v + (size_t)(b * NTOK + c0 + lr) * DIM + h * HD + lc;
        *(float4*)&vs[lr][lc]      = *(const float4*)(vrow);
        *(float4*)&vs[lr][lc + 4]  = *(const float4*)(vrow + 4);
        *(float4*)&vs[lr][lc + 8]  = *(const float4*)(vrow + 8);
        *(float4*)&vs[lr][lc + 12] = *(const float4*)(vrow + 12);
    }
    __syncthreads();

    const int nloc = t & 63;
    const int dgrp = t >> 6;

    for (int d = dgrp; d < 64; d += 4) {
        float accv = 0.0f;
#pragma unroll
        for (int m = 0; m < 64; m++)
            accv += As[m * 64 + nloc] * vs[d][m];
        const int tok = c0 + d;
        float val = (SCALE * accv + vs[d][nloc]) * zs[nloc];
        val *= gg[(size_t)(b * NTOK + tok) * DIM + h * HD + nloc];
        const int row = b * NTOK + h * 256 + (tok >> 4);
        const int col = ((tok & 15) << 6) + nloc;
        Yh[(size_t)row * DIM + col] = __float2half_rn(val);
    }
}

// ---------------------------------------------------------------------------
// Launch — stream-forked DAG
// ---------------------------------------------------------------------------
extern "C" void kernel_launch(void* const* d_in, const int* in_sizes, int n_in,
                              void* d_out, int out_size)
{
    const float* x    = (const float*)d_in[0];
    const float* q_w1 = (const float*)d_in[1];
    const float* q_b1 = (const float*)d_in[2];
    const float* q_w2 = (const float*)d_in[3];
    const float* q_b2 = (const float*)d_in[4];
    const float* k_w1 = (const float*)d_in[5];
    const float* k_b1 = (const float*)d_in[6];
    const float* k_w2 = (const float*)d_in[7];
    const float* k_b2 = (const float*)d_in[8];
    const float* v_w  = (const float*)d_in[9];
    const float* v_b  = (const float*)d_in[10];
    const float* g_w  = (const float*)d_in[11];
    const float* g_b  = (const float*)d_in[12];
    const float* p_w  = (const float*)d_in[13];
    const float* p_b  = (const float*)d_in[14];
    float* out = (float*)d_out;

    __half *xh, *hqh, *hkh, *yh, *wh;
    float *qb, *kb, *vb, *gb, *Ab, *zb, *Apb, *zpb;
    cudaGetSymbolAddress((void**)&xh,  g_x_h);
    cudaGetSymbolAddress((void**)&hqh, g_hq_h);
    cudaGetSymbolAddress((void**)&hkh, g_hk_h);
    cudaGetSymbolAddress((void**)&yh,  g_y_h);
    cudaGetSymbolAddress((void**)&wh,  g_w_h);
    cudaGetSymbolAddress((void**)&qb,  g_q);
    cudaGetSymbolAddress((void**)&kb,  g_k);
    cudaGetSymbolAddress((void**)&vb,  g_v);
    cudaGetSymbolAddress((void**)&gb,  g_g);
    cudaGetSymbolAddress((void**)&Ab,  g_A);
    cudaGetSymbolAddress((void**)&zb,  g_z);
    cudaGetSymbolAddress((void**)&Apb, g_Ap);
    cudaGetSymbolAddress((void**)&zpb, g_zp);

    static bool init_done = false;
    static cudaStream_t s1, s2, s3;
    static cudaEvent_t ev_x, ev_k, ev_v, ev_g;
    if (!init_done) {
        cudaFuncSetAttribute(gemm_mma, cudaFuncAttributeMaxDynamicSharedMemorySize, GSMEM_TOTAL);
        cudaStreamCreateWithFlags(&s1, cudaStreamNonBlocking);
        cudaStreamCreateWithFlags(&s2, cudaStreamNonBlocking);
        cudaStreamCreateWithFlags(&s3, cudaStreamNonBlocking);
        cudaEventCreateWithFlags(&ev_x, cudaEventDisableTiming);
        cudaEventCreateWithFlags(&ev_k, cudaEventDisableTiming);
        cudaEventCreateWithFlags(&ev_v, cudaEventDisableTiming);
        cudaEventCreateWithFlags(&ev_g, cudaEventDisableTiming);
        init_done = true;
    }

    const int WSZ = DIM * DIM;
#define WH(i) (wh + (size_t)(i) * WSZ)

    dim3 ggrid(DIM / 128, MROWS / 128);   // (8, 128)

    // stream0: convert x, then fork
    conv_f2h<<<1184, 256>>>(x, xh, MROWS * DIM / 4);
    cudaEventRecord(ev_x, 0);

    // --- s1: k path ---
    cudaStreamWaitEvent(s1, ev_x, 0);
    conv_f2h<<<592, 256, 0, s1>>>(k_w1, WH(2), WSZ / 4);
    gemm_mma<<<ggrid, 256, GSMEM_TOTAL, s1>>>(xh, WH(2), k_b1, 1, 1, nullptr, hkh);
    conv_f2h<<<592, 256, 0, s1>>>(k_w2, WH(3), WSZ / 4);
    gemm_mma<<<ggrid, 256, GSMEM_TOTAL, s1>>>(hkh, WH(3), k_b2, 2, 0, kb, nullptr);
    cudaEventRecord(ev_k, s1);

    // --- s2: v ---
    cudaStreamWaitEvent(s2, ev_x, 0);
    conv_f2h<<<592, 256, 0, s2>>>(v_w, WH(4), WSZ / 4);
    gemm_mma<<<ggrid, 256, GSMEM_TOTAL, s2>>>(xh, WH(4), v_b, 1, 0, vb, nullptr);
    cudaEventRecord(ev_v, s2);

    // --- s3: g ---
    cudaStreamWaitEvent(s3, ev_x, 0);
    conv_f2h<<<592, 256, 0, s3>>>(g_w, WH(5), WSZ / 4);
    gemm_mma<<<ggrid, 256, GSMEM_TOTAL, s3>>>(xh, WH(5), g_b, 1, 0, gb, nullptr);
    cudaEventRecord(ev_g, s3);

    // --- stream0: q path + p_w conversion ---
    conv_f2h<<<592, 256>>>(q_w1, WH(0), WSZ / 4);
    gemm_mma<<<ggrid, 256, GSMEM_TOTAL>>>(xh, WH(0), q_b1, 1, 1, nullptr, hqh);
    conv_f2h<<<592, 256>>>(q_w2, WH(1), WSZ / 4);
    gemm_mma<<<ggrid, 256, GSMEM_TOTAL>>>(hqh, WH(1), q_b2, 2, 0, qb, nullptr);
    conv_f2h<<<592, 256>>>(p_w, WH(6), WSZ / 4);

    // join k for attention pass 1 (chunked, then reduce)
    cudaStreamWaitEvent(0, ev_k, 0);
    attn_pass1p<<<dim3(BATCH * NHEAD, NCHUNK), 512>>>(qb, kb, Apb, zpb);
    attn_reduce<<<BATCH * NHEAD, 256>>>(Apb, zpb, Ab, zb);

    // join v, g for pass 2
    cudaStreamWaitEvent(0, ev_v, 0);
    cudaStreamWaitEvent(0, ev_g, 0);
    attn_pass2<<<dim3(BATCH * NHEAD, NTOK / 64), 256>>>(vb, gb, Ab, zb, yh);

    // final projection
    gemm_mma<<<ggrid, 256, GSMEM_TOTAL>>>(yh, WH(6), p_b, 0, 0, out, nullptr);
}

// round 10
// speedup vs baseline: 1.5379x; 1.5379x over previous
#include <cuda_runtime.h>
#include <cuda_fp16.h>
#include <math.h>
#include <stdint.h>

// Problem constants
#define BATCH 4
#define NTOK 4096
#define DIM 1024
#define NHEAD 16
#define HD 64
#define MROWS (BATCH * NTOK)          // 16384
#define SCALE 0.125f                  // HD^-0.5
#define NCHUNK 4

// ---------------------------------------------------------------------------
// Scratch buffers
// ---------------------------------------------------------------------------
__device__ __half g_x_h [MROWS * DIM];
__device__ __half g_hq_h[MROWS * DIM];
__device__ __half g_hk_h[MROWS * DIM];
__device__ __half g_y_h [MROWS * DIM];
__device__ __half g_q [MROWS * DIM];
__device__ __half g_k [MROWS * DIM];
__device__ __half g_v [MROWS * DIM];
__device__ __half g_g [MROWS * DIM];
__device__ float g_A [BATCH * NHEAD * HD * HD];
__device__ float g_z [BATCH * NHEAD * HD];
__device__ float g_Ap[NCHUNK * BATCH * NHEAD * HD * HD];
__device__ float g_zp[NCHUNK * BATCH * NHEAD * HD];
__device__ __half g_w_h [7 * DIM * DIM];

// ---------------------------------------------------------------------------
// PTX helpers (sm_80+ portable)
// ---------------------------------------------------------------------------
__device__ __forceinline__ uint32_t smem_u32(const void* p) {
    uint32_t a;
    asm("{ .reg .u64 t; cvta.to.shared.u64 t, %1; cvt.u32.u64 %0, t; }" : "=r"(a) : "l"(p));
    return a;
}
#define SWZ(o) ((o) ^ (((o) >> 3) & 0x70))

__device__ __forceinline__ void cp16(uint32_t saddr, const void* g) {
    asm volatile("cp.async.cg.shared.global [%0], [%1], 16;" :: "r"(saddr), "l"(g));
}
#define CP_COMMIT() asm volatile("cp.async.commit_group;" ::: "memory")
#define CP_WAIT(N)  asm volatile("cp.async.wait_group %0;" :: "n"(N) : "memory")

#define LDSM4(r, a) \
    asm volatile("ldmatrix.sync.aligned.m8n8.x4.shared.b16 {%0,%1,%2,%3}, [%4];" \
        : "=r"((r)[0]), "=r"((r)[1]), "=r"((r)[2]), "=r"((r)[3]) : "r"(a))

#define MMA16816F(c, a, b) \
    asm volatile("mma.sync.aligned.m16n8k16.row.col.f32.f16.f16.f32 " \
        "{%0,%1,%2,%3}, {%4,%5,%6,%7}, {%8,%9}, {%0,%1,%2,%3};" \
        : "+f"((c)[0]), "+f"((c)[1]), "+f"((c)[2]), "+f"((c)[3]) \
        : "r"((a)[0]), "r"((a)[1]), "r"((a)[2]), "r"((a)[3]), \
          "r"((b)[0]), "r"((b)[1]))

// ---------------------------------------------------------------------------
// Activations
// ---------------------------------------------------------------------------
__device__ __forceinline__ float gelu_f(float x) {
    return 0.5f * x * (1.0f + erff(x * 0.70710678118654752440f));
}
__device__ __forceinline__ float softplus_f(float x) {
    return fmaxf(x, 0.0f) + log1pf(__expf(-fabsf(x)));
}
__device__ __forceinline__ uint32_t pack2h(float a, float b) {
    __half2 h = __halves2half2(__float2half_rn(a), __float2half_rn(b));
    return *(uint32_t*)&h;
}

// ---------------------------------------------------------------------------
// fp32 -> fp16 convert
// ---------------------------------------------------------------------------
__global__ __launch_bounds__(256)
void conv_f2h(const float* __restrict__ src, __half* __restrict__ dst, int n4)
{
    const int stride = gridDim.x * blockDim.x;
    for (int i = blockIdx.x * blockDim.x + threadIdx.x; i < n4; i += stride) {
        float4 v = ((const float4*)src)[i];
        uint2 d;
        d.x = pack2h(v.x, v.y);
        d.y = pack2h(v.z, v.w);
        ((uint2*)dst)[i] = d;
    }
}

// ---------------------------------------------------------------------------
// HMMA fp16 single-term GEMM (R8 core, unchanged)
// ---------------------------------------------------------------------------
#define TILE_B 16384
#define STAGE_B (2 * TILE_B)
#define NSTAGE 3
#define GSMEM_TOTAL (NSTAGE * STAGE_B)  // 98304

__global__ __launch_bounds__(256, 2)
void gemm_mma(const __half* __restrict__ A, const __half* __restrict__ Wh,
              const float* __restrict__ bias, int act, int outmode,
              float* __restrict__ Cf, __half* __restrict__ Ch)
{
    extern __shared__ char smem[];
    const uint32_t sb = smem_u32(smem);
    const int t    = threadIdx.x;
    const int lane = t & 31;
    const int w    = t >> 5;
    const int wm   = w & 3;
    const int wn   = w >> 2;
    const int m0   = blockIdx.y * 128;
    const int n0   = blockIdx.x * 128;

    const int lrow = t >> 3;
    const int lu   = t & 7;

    auto issue = [&](int stage, int kc) {
        const uint32_t sbase = sb + stage * STAGE_B;
        const int kbase = kc * 64 + lu * 8;
#pragma unroll
        for (int i = 0; i < 4; i++) {
            const int row = lrow + i * 32;
            const uint32_t soff = SWZ((uint32_t)(row * 128 + lu * 16));
            cp16(sbase + soff,          A  + (size_t)(m0 + row) * DIM + kbase);
            cp16(sbase + TILE_B + soff, Wh + (size_t)(n0 + row) * DIM + kbase);
        }
        CP_COMMIT();
    };

    issue(0, 0);
    issue(1, 1);

    float acc[2][8][4];
#pragma unroll
    for (int im = 0; im < 2; im++)
#pragma unroll
        for (int in = 0; in < 8; in++)
#pragma unroll
            for (int j = 0; j < 4; j++) acc[im][in][j] = 0.0f;

    const int g  = lane >> 3;
    const int rr = lane & 7;

    for (int kc = 0; kc < 16; kc++) {
        if (kc == 15) { CP_WAIT(0); } else { CP_WAIT(1); }
        __syncthreads();
        if (kc + 2 < 16) issue((kc + 2) % NSTAGE, kc + 2);

        const uint32_t st = sb + (kc % NSTAGE) * STAGE_B;
#pragma unroll
        for (int kk = 0; kk < 4; kk++) {
            const int ku = kk * 2 + (g >> 1);
            uint32_t ah[2][4];
#pragma unroll
            for (int im = 0; im < 2; im++) {
                const int row = wm * 32 + im * 16 + (g & 1) * 8 + rr;
                const uint32_t off = SWZ((uint32_t)(row * 128 + ku * 16));
                LDSM4(ah[im], st + off);
            }
            uint32_t bh[8][2];
#pragma unroll
            for (int in2 = 0; in2 < 4; in2++) {
                const int row = wn * 64 + in2 * 16 + (g & 1) * 8 + rr;
                const uint32_t off = SWZ((uint32_t)(row * 128 + ku * 16));
                uint32_t qh[4];
                LDSM4(qh, st + TILE_B + off);
                bh[2 * in2][0] = qh[0]; bh[2 * in2][1] = qh[2];
                bh[2 * in2 + 1][0] = qh[1]; bh[2 * in2 + 1][1] = qh[3];
            }
#pragma unroll
            for (int im = 0; im < 2; im++)
#pragma unroll
                for (int in = 0; in < 8; in++)
                    MMA16816F(acc[im][in], ah[im], bh[in]);
        }
    }

    const int r0 = lane >> 2;
    const int c0 = (lane & 3) * 2;
#pragma unroll
    for (int im = 0; im < 2; im++) {
#pragma unroll
        for (int in = 0; in < 8; in++) {
            const int ncol = n0 + wn * 64 + in * 8 + c0;
            const float b0 = __ldg(&bias[ncol]);
            const float b1 = __ldg(&bias[ncol + 1]);
#pragma unroll
            for (int half = 0; half < 2; half++) {
                const int mrow = m0 + wm * 32 + im * 16 + r0 + half * 8;
                float v0 = acc[im][in][half * 2]     + b0;
                float v1 = acc[im][in][half * 2 + 1] + b1;
                if (act == 1)      { v0 = gelu_f(v0);     v1 = gelu_f(v1); }
                else if (act == 2) { v0 = softplus_f(v0); v1 = softplus_f(v1); }
                if (outmode == 0) {
                    *(float2*)(Cf + (size_t)mrow * DIM + ncol) = make_float2(v0, v1);
                } else {
                    *(__half2*)(Ch + (size_t)mrow * DIM + ncol) =
                        __halves2half2(__float2half_rn(v0), __float2half_rn(v1));
                }
            }
        }
    }
}

// ---------------------------------------------------------------------------
// Attention pass 1 (partial) — fp16 q/k inputs, fp32 compute
// ---------------------------------------------------------------------------
__global__ __launch_bounds__(512)
void attn_pass1p(const __half* __restrict__ q, const __half* __restrict__ k,
                 float* __restrict__ Ap, float* __restrict__ Zp)
{
    const int bh = blockIdx.x;
    const int ch = blockIdx.y;
    const int b  = bh >> 4;
    const int h  = bh & 15;
    const __half* qb = q + (size_t)b * NTOK * DIM + h * HD;
    const __half* kb = k + (size_t)b * NTOK * DIM + h * HD;

    __shared__ float qs[64][64];
    __shared__ float ks[64][64];
    __shared__ float ksum[64];

    const int t  = threadIdx.x;
    const int n  = t >> 3;
    const int m0 = (t & 7) << 3;
    const int lr = t >> 3;          // 0..63
    const int lc = (t & 7) << 3;    // 0..56 step 8 (halves)

    float acc[8] = {0, 0, 0, 0, 0, 0, 0, 0};
    float zacc = 0.0f;
    const bool zowner = ((t & 7) == 0);

    const int cbeg = ch * (NTOK / NCHUNK);
    const int cend = cbeg + (NTOK / NCHUNK);
    for (int c0 = cbeg; c0 < cend; c0 += 64) {
        // each thread loads 8 halves (one uint4) of q and k
        const uint4 qr = *(const uint4*)(qb + (size_t)(c0 + lr) * DIM + lc);
        const uint4 kr = *(const uint4*)(kb + (size_t)(c0 + lr) * DIM + lc);
        __syncthreads();
        {
            const __half2* qp = (const __half2*)&qr;
            const __half2* kp = (const __half2*)&kr;
#pragma unroll
            for (int j = 0; j < 4; j++) {
                float2 qf = __half22float2(qp[j]);
                float2 kf = __half22float2(kp[j]);
                qs[lr][lc + 2 * j]     = qf.x;
                qs[lr][lc + 2 * j + 1] = qf.y;
                ks[lr][lc + 2 * j]     = kf.x;
                ks[lr][lc + 2 * j + 1] = kf.y;
            }
        }
        __syncthreads();
        if (t < 64) {
            float s = 0.0f;
#pragma unroll
            for (int m = 0; m < 64; m++) s += ks[t][(m + t) & 63];
            ksum[t] = s;
        }
        __syncthreads();

#pragma unroll 4
        for (int c = 0; c < 64; c++) {
            float qv = qs[c][n];
            float4 k4a = *(const float4*)&ks[c][m0];
            float4 k4b = *(const float4*)&ks[c][m0 + 4];
            acc[0] += qv * k4a.x; acc[1] += qv * k4a.y;
            acc[2] += qv * k4a.z; acc[3] += qv * k4a.w;
            acc[4] += qv * k4b.x; acc[5] += qv * k4b.y;
            acc[6] += qv * k4b.z; acc[7] += qv * k4b.w;
            if (zowner) zacc += qv * ksum[c];
        }
    }

    float* Abh = Ap + ((size_t)ch * 64 + bh) * HD * HD;
#pragma unroll
    for (int j = 0; j < 8; j++)
        Abh[(m0 + j) * HD + n] = acc[j];
    if (zowner)
        Zp[((size_t)ch * 64 + bh) * HD + n] = zacc;
}

__global__ __launch_bounds__(256)
void attn_reduce(const float* __restrict__ Ap, const float* __restrict__ Zp,
                 float* __restrict__ gA, float* __restrict__ gZ)
{
    const int bh = blockIdx.x;
    const int t  = threadIdx.x;
    for (int i = t; i < HD * HD; i += 256) {
        float s = 0.0f;
#pragma unroll
        for (int c = 0; c < NCHUNK; c++)
            s += Ap[((size_t)c * 64 + bh) * HD * HD + i];
        gA[(size_t)bh * HD * HD + i] = s;
    }
    if (t < HD) {
        float s = 0.0f;
#pragma unroll
        for (int c = 0; c < NCHUNK; c++)
            s += Zp[((size_t)c * 64 + bh) * HD + t];
        gZ[bh * HD + t] = 1.0f / (SCALE * s + (float)DIM);
    }
}

// ---------------------------------------------------------------------------
// Attention pass 2 — fp16 v/g inputs, fp32 compute, fp16 scrambled output
// ---------------------------------------------------------------------------
__global__ __launch_bounds__(256)
void attn_pass2(const __half* __restrict__ v, const __half* __restrict__ gg,
                const float* __restrict__ gA, const float* __restrict__ gZ,
                __half* __restrict__ Yh)
{
    const int bh = blockIdx.x;
    const int b  = bh >> 4;
    const int h  = bh & 15;
    const int c0 = blockIdx.y * 64;

    __shared__ float As[HD * HD];
    __shared__ float vs[64][64];
    __shared__ float zs[64];

    const int t = threadIdx.x;

    const float4* Asrc = (const float4*)(gA + (size_t)bh * HD * HD);
#pragma unroll
    for (int i = t; i < HD * HD / 4; i += 256)
        ((float4*)As)[i] = Asrc[i];
    if (t < 64) zs[t] = gZ[bh * HD + t];

    {
        const int lr = t >> 2;          // 0..63
        const int lc = (t & 3) << 4;    // 0,16,32,48 (halves)
        const __half* vrow = v + (size_t)(b * NTOK + c0 + lr) * DIM + h * HD + lc;
        uint4 r0 = *(const uint4*)(vrow);
        uint4 r1 = *(const uint4*)(vrow + 8);
        const __half2* p0 = (const __half2*)&r0;
        const __half2* p1 = (const __half2*)&r1;
#pragma unroll
        for (int j = 0; j < 4; j++) {
            float2 f0 = __half22float2(p0[j]);
            float2 f1 = __half22float2(p1[j]);
            vs[lr][lc + 2 * j]         = f0.x;
            vs[lr][lc + 2 * j + 1]     = f0.y;
            vs[lr][lc + 8 + 2 * j]     = f1.x;
            vs[lr][lc + 8 + 2 * j + 1] = f1.y;
        }
    }
    __syncthreads();

    const int nloc = t & 63;
    const int dgrp = t >> 6;

    for (int d = dgrp; d < 64; d += 4) {
        float accv = 0.0f;
#pragma unroll
        for (int m = 0; m < 64; m++)
            accv += As[m * 64 + nloc] * vs[d][m];
        const int tok = c0 + d;
        float val = (SCALE * accv + vs[d][nloc]) * zs[nloc];
        val *= __half2float(gg[(size_t)(b * NTOK + tok) * DIM + h * HD + nloc]);
        const int row = b * NTOK + h * 256 + (tok >> 4);
        const int col = ((tok & 15) << 6) + nloc;
        Yh[(size_t)row * DIM + col] = __float2half_rn(val);
    }
}

// ---------------------------------------------------------------------------
// Launch — convs hoisted so launch #6 is gemm_mma (for ncu -s 5 -c 1)
// ---------------------------------------------------------------------------
extern "C" void kernel_launch(void* const* d_in, const int* in_sizes, int n_in,
                              void* d_out, int out_size)
{
    const float* x    = (const float*)d_in[0];
    const float* q_w1 = (const float*)d_in[1];
    const float* q_b1 = (const float*)d_in[2];
    const float* q_w2 = (const float*)d_in[3];
    const float* q_b2 = (const float*)d_in[4];
    const float* k_w1 = (const float*)d_in[5];
    const float* k_b1 = (const float*)d_in[6];
    const float* k_w2 = (const float*)d_in[7];
    const float* k_b2 = (const float*)d_in[8];
    const float* v_w  = (const float*)d_in[9];
    const float* v_b  = (const float*)d_in[10];
    const float* g_w  = (const float*)d_in[11];
    const float* g_b  = (const float*)d_in[12];
    const float* p_w  = (const float*)d_in[13];
    const float* p_b  = (const float*)d_in[14];
    float* out = (float*)d_out;

    __half *xh, *hqh, *hkh, *yh, *wh, *qb, *kb, *vb, *gb;
    float *Ab, *zb, *Apb, *zpb;
    cudaGetSymbolAddress((void**)&xh,  g_x_h);
    cudaGetSymbolAddress((void**)&hqh, g_hq_h);
    cudaGetSymbolAddress((void**)&hkh, g_hk_h);
    cudaGetSymbolAddress((void**)&yh,  g_y_h);
    cudaGetSymbolAddress((void**)&wh,  g_w_h);
    cudaGetSymbolAddress((void**)&qb,  g_q);
    cudaGetSymbolAddress((void**)&kb,  g_k);
    cudaGetSymbolAddress((void**)&vb,  g_v);
    cudaGetSymbolAddress((void**)&gb,  g_g);
    cudaGetSymbolAddress((void**)&Ab,  g_A);
    cudaGetSymbolAddress((void**)&zb,  g_z);
    cudaGetSymbolAddress((void**)&Apb, g_Ap);
    cudaGetSymbolAddress((void**)&zpb, g_zp);

    static bool init_done = false;
    static cudaStream_t s1, s2, s3;
    static cudaEvent_t ev_x, ev_k, ev_v, ev_g;
    if (!init_done) {
        cudaFuncSetAttribute(gemm_mma, cudaFuncAttributeMaxDynamicSharedMemorySize, GSMEM_TOTAL);
        cudaStreamCreateWithFlags(&s1, cudaStreamNonBlocking);
        cudaStreamCreateWithFlags(&s2, cudaStreamNonBlocking);
        cudaStreamCreateWithFlags(&s3, cudaStreamNonBlocking);
        cudaEventCreateWithFlags(&ev_x, cudaEventDisableTiming);
        cudaEventCreateWithFlags(&ev_k, cudaEventDisableTiming);
        cudaEventCreateWithFlags(&ev_v, cudaEventDisableTiming);
        cudaEventCreateWithFlags(&ev_g, cudaEventDisableTiming);
        init_done = true;
    }

    const int WSZ = DIM * DIM;
#define WH(i) (wh + (size_t)(i) * WSZ)

    dim3 ggrid(DIM / 128, MROWS / 128);   // (8, 128)

    // #1: x convert (s0), record event
    conv_f2h<<<1184, 256>>>(x, xh, MROWS * DIM / 4);
    cudaEventRecord(ev_x, 0);

    // #2-#4: first-layer weight converts on side streams (independent of x)
    conv_f2h<<<592, 256, 0, s1>>>(k_w1, WH(2), WSZ / 4);
    cudaStreamWaitEvent(s1, ev_x, 0);
    conv_f2h<<<592, 256, 0, s2>>>(v_w, WH(4), WSZ / 4);
    cudaStreamWaitEvent(s2, ev_x, 0);
    conv_f2h<<<592, 256, 0, s3>>>(g_w, WH(5), WSZ / 4);
    cudaStreamWaitEvent(s3, ev_x, 0);

    // #5: q_w1 convert (s0)
    conv_f2h<<<592, 256>>>(q_w1, WH(0), WSZ / 4);

    // #6: FIRST GEMM — this is the launch ncu profiles
    gemm_mma<<<ggrid, 256, GSMEM_TOTAL>>>(xh, WH(0), q_b1, 1, 1, nullptr, hqh);

    // side-stream first-layer GEMMs
    gemm_mma<<<ggrid, 256, GSMEM_TOTAL, s1>>>(xh, WH(2), k_b1, 1, 1, nullptr, hkh);
    gemm_mma<<<ggrid, 256, GSMEM_TOTAL, s2>>>(xh, WH(4), v_b, 1, 1, nullptr, vb);
    cudaEventRecord(ev_v, s2);
    gemm_mma<<<ggrid, 256, GSMEM_TOTAL, s3>>>(xh, WH(5), g_b, 1, 1, nullptr, gb);
    cudaEventRecord(ev_g, s3);

    // second layers
    conv_f2h<<<592, 256>>>(q_w2, WH(1), WSZ / 4);
    gemm_mma<<<ggrid, 256, GSMEM_TOTAL>>>(hqh, WH(1), q_b2, 2, 1, nullptr, qb);
    conv_f2h<<<592, 256, 0, s1>>>(k_w2, WH(3), WSZ / 4);
    gemm_mma<<<ggrid, 256, GSMEM_TOTAL, s1>>>(hkh, WH(3), k_b2, 2, 1, nullptr, kb);
    cudaEventRecord(ev_k, s1);

    // p_w convert while waiting
    conv_f2h<<<592, 256>>>(p_w, WH(6), WSZ / 4);

    // attention
    cudaStreamWaitEvent(0, ev_k, 0);
    attn_pass1p<<<dim3(BATCH * NHEAD, NCHUNK), 512>>>(qb, kb, Apb, zpb);
    attn_reduce<<<BATCH * NHEAD, 256>>>(Apb, zpb, Ab, zb);

    cudaStreamWaitEvent(0, ev_v, 0);
    cudaStreamWaitEvent(0, ev_g, 0);
    attn_pass2<<<dim3(BATCH * NHEAD, NTOK / 64), 256>>>(vb, gb, Ab, zb, yh);

    // final projection (fp32 out)
    gemm_mma<<<ggrid, 256, GSMEM_TOTAL>>>(yh, WH(6), p_b, 0, 0, out, nullptr);
}